// round 15
// baseline (speedup 1.0000x reference)
#include <cuda_runtime.h>
#include <cuda_fp16.h>
#include <cstdint>

// Problem constants
#define MROWS   32768
#define DIM     768
#define VPOS    10240
#define POS_OFF ((size_t)VPOS * DIM)

// GEMM tiling: CTA 128x128, 8 warps (2m x 4n), warp tile 64x32
// fp16 operands, fp32 accumulate. BK=64, 3-stage pipeline fed by cp.async.bulk
// (one 16KB bulk per matrix per tile) + mbarrier complete_tx.
// Operands live in gmem in TILE-MAJOR layout: tile (128 rows x 64 k) = 16KB
// contiguous, with k-permute (k=16g+8h+2c+e -> 8c+4g+2h+e per 32-chunk) and
// row-parity 64B-chunk swizzle pre-baked, so smem is a verbatim copy.
#define BM 128
#define BN 128
#define BK 64
#define NKT (DIM / BK)              // 12
#define TB 16384                    // bytes per operand tile
#define STAGE_B (2 * TB)            // A + B = 32768
#define NSTAGE 3
#define HDR 1024                    // mbarriers live here
#define SMEM_BYTES (HDR + NSTAGE * STAGE_B)   // 99328

// Fused prologue block ranges
#define XPREP_BLOCKS ((MROWS * 96) / 256)   // 12288
#define PREP_BLOCKS  DIM                    // 768
#define NORM_BLOCKS  (MROWS / 256)          // 128
#define PRO_BLOCKS   (XPREP_BLOCKS + PREP_BLOCKS + NORM_BLOCKS)

// Output layout (flattened concat of the reference tuple, as float32)
#define OUT_Y     ((size_t)MROWS * DIM)
#define OUT_PID   ((size_t)MROWS * 2)
#define OUT_TOTAL (OUT_Y + OUT_PID + (size_t)MROWS)

// Device scratch (tile-major operand buffers)
__device__ __align__(128) unsigned char g_Xb[(size_t)(MROWS / 128) * NKT * TB]; // 48MB
__device__ __align__(128) unsigned char g_Wb[(size_t)(DIM / 128) * NKT * TB];   // 1.125MB
__device__ float g_bias[DIM];       // -sum_k W[d,k]
__device__ int g_pid0[MROWS];
__device__ int g_pid1[MROWS];
__device__ unsigned char g_ok[MROWS];

__device__ __forceinline__ void mma_fp16(float* c,
                                         uint32_t a0, uint32_t a1, uint32_t a2, uint32_t a3,
                                         uint32_t b0, uint32_t b1) {
    asm volatile(
        "mma.sync.aligned.m16n8k16.row.col.f32.f16.f16.f32 "
        "{%0,%1,%2,%3}, {%4,%5,%6,%7}, {%8,%9}, {%0,%1,%2,%3};\n"
        : "+f"(c[0]), "+f"(c[1]), "+f"(c[2]), "+f"(c[3])
        : "r"(a0), "r"(a1), "r"(a2), "r"(a3), "r"(b0), "r"(b1));
}

__device__ __forceinline__ void bulk_g2s(uint32_t dst, const void* src, uint32_t bytes, uint32_t mbar) {
    asm volatile(
        "cp.async.bulk.shared::cluster.global.mbarrier::complete_tx::bytes [%0], [%1], %2, [%3];"
        :: "r"(dst), "l"(src), "r"(bytes), "r"(mbar) : "memory");
}

__device__ __forceinline__ void mbar_init(uint32_t a, uint32_t cnt) {
    asm volatile("mbarrier.init.shared.b64 [%0], %1;" :: "r"(a), "r"(cnt) : "memory");
}
__device__ __forceinline__ void mbar_expect_tx(uint32_t a, uint32_t bytes) {
    asm volatile("mbarrier.arrive.expect_tx.shared.b64 _, [%0], %1;" :: "r"(a), "r"(bytes) : "memory");
}
__device__ __forceinline__ void mbar_wait(uint32_t a, uint32_t parity) {
    asm volatile(
        "{\n\t.reg .pred P;\n\t"
        "WL_%=:\n\t"
        "mbarrier.try_wait.parity.acquire.cta.shared::cta.b64 P, [%0], %1, 0x989680;\n\t"
        "@P bra WD_%=;\n\t"
        "bra WL_%=;\n\t"
        "WD_%=:\n\t}"
        :: "r"(a), "r"(parity) : "memory");
}

// ---------------------------------------------------------------------------
// Fused prologue: one launch, three independent block ranges.
//   [0, XPREP_BLOCKS)            : fp16-convert + permute + TILE x into g_Xb
//   [XPREP_BLOCKS, +PREP_BLOCKS) : weight permute/scale/round + TILE + bias
//   [rest, +NORM_BLOCKS)         : self-detecting coord/valid normalize + aux
// ---------------------------------------------------------------------------
__global__ void __launch_bounds__(256) prologue_kernel(
    const float* __restrict__ x,
    const float* __restrict__ W,
    const void*  coordp,
    const void*  validp,
    float* __restrict__ out_pid,
    float* __restrict__ out_pad,
    int do_aux)
{
    const int bid = blockIdx.x;
    const int tid = threadIdx.x;

    if (bid < XPREP_BLOCKS) {
        // ---- xprep: k=16g+8h+2c+e -> phys=8c+4g+2h+e, tiled destination ----
        unsigned int idx = bid * 256 + tid;              // < MROWS*96
        unsigned int row = idx / 96;
        unsigned int u = idx - row * 96;
        unsigned int ci = u >> 2, c = u & 3;
        const float* src = x + (size_t)row * DIM + ci * 32 + 2 * c;
        float2 p00 = *reinterpret_cast<const float2*>(src);
        float2 p01 = *reinterpret_cast<const float2*>(src + 8);
        float2 p10 = *reinterpret_cast<const float2*>(src + 16);
        float2 p11 = *reinterpret_cast<const float2*>(src + 24);
        __half2 h00 = __floats2half2_rn(p00.x, p00.y);
        __half2 h01 = __floats2half2_rn(p01.x, p01.y);
        __half2 h10 = __floats2half2_rn(p10.x, p10.y);
        __half2 h11 = __floats2half2_rn(p11.x, p11.y);
        uint4 o;
        o.x = *reinterpret_cast<uint32_t*>(&h00);
        o.y = *reinterpret_cast<uint32_t*>(&h01);
        o.z = *reinterpret_cast<uint32_t*>(&h10);
        o.w = *reinterpret_cast<uint32_t*>(&h11);
        unsigned int rb = row >> 7, r = row & 127;
        unsigned int kt = ci >> 1, ch = ci & 1;
        size_t off = ((size_t)(rb * NKT + kt) << 14) + r * 128 + ((ch ^ (r & 1)) << 6) + c * 16;
        *reinterpret_cast<uint4*>(g_Xb + off) = o;
        return;
    }

    if (bid < XPREP_BLOCKS + PREP_BLOCKS) {
        // ---- prep: weights (tiled destination) ----
        int d = bid - XPREP_BLOCKS;
        const float* wrow = W + (size_t)d * DIM;
        int nb = d >> 7, r = d & 127;
        __shared__ float red[256];
        float s = 0.f;
        for (int jp = tid; jp < DIM; jp += 256) {
            int ci = jp >> 5, p = jp & 31;
            int c = p >> 3, g = (p >> 2) & 1, h = (p >> 1) & 1, e = p & 1;
            int j = ci * 32 + 16 * g + 8 * h + 2 * c + e;  // logical column
            int c3 = j % 3;
            int tt = j / 3;
            int pw = tt & 15;
            int ph = tt >> 4;
            int k = c3 * 256 + ph * 16 + pw;
            float w = wrow[k];
            s += w;
            int kt = ci >> 1, ch = ci & 1;
            size_t off = ((size_t)(nb * NKT + kt) << 14) + r * 128 + ((ch ^ (r & 1)) << 6) + p * 2;
            *reinterpret_cast<__half*>(g_Wb + off) = __float2half_rn(2.0f * w);
        }
        red[tid] = s;
        __syncthreads();
        for (int off = 128; off > 0; off >>= 1) {
            if (tid < off) red[tid] += red[tid + off];
            __syncthreads();
        }
        if (tid == 0) g_bias[d] = -red[0];
        return;
    }

    // ---- norm (+self-detect) + aux ----
    {
        __shared__ unsigned int s_or_all, s_or_odd, s_vb_or, s_vb_gt1;
        __shared__ int sh_cf, sh_vf;
        if (tid == 0) { s_or_all = 0; s_or_odd = 0; s_vb_or = 0; s_vb_gt1 = 0; }
        __syncthreads();

        const unsigned int* cw = (const unsigned int*)coordp;
        unsigned int oa = 0, oo = 0;
        for (int i = tid; i < 2048; i += 256) {
            unsigned int w = cw[i];
            oa |= w;
            if (i & 1) oo |= w;
        }
        atomicOr(&s_or_all, oa);
        atomicOr(&s_or_odd, oo);

        const unsigned char* vb = (const unsigned char*)validp;
        unsigned int vo = 0, vg = 0;
        for (int i = tid; i < 4096; i += 256) {
            unsigned char b = vb[i];
            if (i & 3) vo |= b;
            if (b > 1) vg = 1;
        }
        atomicOr(&s_vb_or, vo);
        atomicOr(&s_vb_gt1, vg);
        __syncthreads();

        if (tid == 0) {
            sh_cf = (s_or_all >= 0x10000u) ? 2 : (s_or_odd == 0 ? 1 : 0);
            sh_vf = s_vb_gt1 ? 2 : (s_vb_or == 0 ? 0 : 1);
        }
        __syncthreads();
        int cf = sh_cf, vf = sh_vf;

        int i = (bid - XPREP_BLOCKS - PREP_BLOCKS) * 256 + tid;   // < MROWS
        int c0, c1;
        if (cf == 1) {
            const long long* c = (const long long*)coordp;
            c0 = (int)c[2LL * i]; c1 = (int)c[2LL * i + 1];
        } else if (cf == 2) {
            const float* c = (const float*)coordp;
            c0 = (int)c[2LL * i]; c1 = (int)c[2LL * i + 1];
        } else {
            const int* c = (const int*)coordp;
            c0 = c[2 * i]; c1 = c[2 * i + 1];
        }
        g_pid0[i] = c1 > 0 ? c1 : 0;
        g_pid1[i] = c0 > 0 ? c0 : 0;

        bool v;
        if (vf == 0)      v = ((const int*)validp)[i] != 0;
        else if (vf == 2) v = ((const float*)validp)[i] != 0.0f;
        else              v = ((const unsigned char*)validp)[i] != 0;
        g_ok[i] = v ? 1 : 0;

        if (do_aux) {
            out_pid[2LL * i]     = (float)c1;
            out_pid[2LL * i + 1] = (float)c0;
            out_pad[i] = v ? 0.0f : 1.0f;
        }
    }
}

// ---------------------------------------------------------------------------
// Main fused GEMM: y = Xh @ Wh^T + bias + pos(gather), fp16 m16n8k16 warp MMA
// grid (6, 256), 256 threads. 3-stage pipeline fed by cp.async.bulk + mbarrier.
// ---------------------------------------------------------------------------
__global__ void __launch_bounds__(256, 2)
gemm_kernel(const float* __restrict__ pos_table,
            float* __restrict__ out) {
    extern __shared__ char smem[];
    const uint32_t sb = (uint32_t)__cvta_generic_to_shared(smem);
    const int tid = threadIdx.x;

    const int lane = tid & 31;
    const int warp = tid >> 5;
    const int wm = warp & 1;   // 0..1  (m, 64 rows each)
    const int wn = warp >> 1;  // 0..3  (n, 32 cols each)
    const int q = lane >> 2;   // 0..7
    const int c = lane & 3;    // 0..3
    const int parq = q & 1;

    const unsigned char* Asrc = g_Xb + (size_t)blockIdx.y * NKT * TB;
    const unsigned char* Bsrc = g_Wb + (size_t)blockIdx.x * NKT * TB;

    // mbarrier init (count 1: the expect_tx arrival)
    if (tid == 0) {
        for (int i = 0; i < NSTAGE; i++) mbar_init(sb + 8 * i, 1);
        asm volatile("fence.proxy.async.shared::cta;" ::: "memory");
    }
    __syncthreads();

    auto issue = [&](int kt, int slot) {
        if (tid == 0) {
            uint32_t mb = sb + 8 * slot;
            uint32_t st = sb + HDR + slot * STAGE_B;
            mbar_expect_tx(mb, STAGE_B);
            bulk_g2s(st,      Asrc + (size_t)kt * TB, TB, mb);
            bulk_g2s(st + TB, Bsrc + (size_t)kt * TB, TB, mb);
        }
    };

    issue(0, 0);
    issue(1, 1);

    float acc[4][4][4];
    #pragma unroll
    for (int a = 0; a < 4; a++)
        #pragma unroll
        for (int b = 0; b < 4; b++)
            #pragma unroll
            for (int k = 0; k < 4; k++) acc[a][b][k] = 0.f;

    // Prefetch epilogue row metadata
    int ep_p0[8], ep_p1[8];
    unsigned char ep_ok[8];
    {
        const int gm0 = blockIdx.y * BM + wm * 64;
        #pragma unroll
        for (int im = 0; im < 4; im++) {
            #pragma unroll
            for (int half = 0; half < 2; half++) {
                int r = gm0 + im * 16 + q + half * 8;
                ep_p0[im * 2 + half] = g_pid0[r];
                ep_p1[im * 2 + half] = g_pid1[r];
                ep_ok[im * 2 + half] = g_ok[r];
            }
        }
    }

    for (int kt = 0; kt < NKT; kt++) {
        const int slot = kt % NSTAGE;
        mbar_wait(sb + 8 * slot, (uint32_t)((kt / NSTAGE) & 1));
        __syncthreads();           // all warps done reading slot (kt-1) -> safe to refill
        if (kt + 2 < NKT) issue(kt + 2, (kt + 2) % NSTAGE);

        const char* Ss = smem + HDR + slot * STAGE_B;
        const char* Als = Ss + (wm * 64 + q) * 128 + c * 16;
        const char* Bls = Ss + TB + (wn * 32 + q) * 128 + c * 16;

        #pragma unroll
        for (int ci = 0; ci < 2; ci++) {
            const int g = ((ci ^ parq) << 6);   // swizzled 32-chunk offset (bytes)
            uint4 Aq[4][2];
            uint4 Bq[4];
            #pragma unroll
            for (int im = 0; im < 4; im++) {
                Aq[im][0] = *reinterpret_cast<const uint4*>(Als + im * 2048 + g);
                Aq[im][1] = *reinterpret_cast<const uint4*>(Als + im * 2048 + 1024 + g);
            }
            #pragma unroll
            for (int in = 0; in < 4; in++)
                Bq[in] = *reinterpret_cast<const uint4*>(Bls + in * 1024 + g);

            #pragma unroll
            for (int im = 0; im < 4; im++)
                #pragma unroll
                for (int in = 0; in < 4; in++)
                    mma_fp16(acc[im][in],
                             Aq[im][0].x, Aq[im][1].x, Aq[im][0].y, Aq[im][1].y,
                             Bq[in].x, Bq[in].y);
            #pragma unroll
            for (int im = 0; im < 4; im++)
                #pragma unroll
                for (int in = 0; in < 4; in++)
                    mma_fp16(acc[im][in],
                             Aq[im][0].z, Aq[im][1].z, Aq[im][0].w, Aq[im][1].w,
                             Bq[in].z, Bq[in].w);
        }
    }

    // Epilogue: + bias + pos gather, write float2
    const int gm0 = blockIdx.y * BM + wm * 64;
    const int gn0 = blockIdx.x * BN + wn * 32;

    #pragma unroll
    for (int im = 0; im < 4; im++) {
        int rbase = gm0 + im * 16 + q;
        #pragma unroll
        for (int half = 0; half < 2; half++) {
            int r = rbase + half * 8;
            int p0 = ep_p0[im * 2 + half];
            int p1 = ep_p1[im * 2 + half];
            bool v = (ep_ok[im * 2 + half] != 0);
            const float* t0 = pos_table + (size_t)p0 * DIM;
            const float* t1 = pos_table + POS_OFF + (size_t)p1 * DIM;
            float* orow = out + (size_t)r * DIM;
            #pragma unroll
            for (int in = 0; in < 4; in++) {
                int d = gn0 + in * 8 + c * 2;
                float v0 = acc[im][in][half * 2 + 0] + g_bias[d];
                float v1 = acc[im][in][half * 2 + 1] + g_bias[d + 1];
                if (v) {
                    v0 += t0[d] + t1[d];
                    v1 += t0[d + 1] + t1[d + 1];
                }
                float2 o; o.x = v0; o.y = v1;
                *reinterpret_cast<float2*>(&orow[d]) = o;
            }
        }
    }
}

extern "C" void kernel_launch(void* const* d_in, const int* in_sizes, int n_in,
                              void* d_out, int out_size) {
    const float* x     = (const float*)d_in[0];
    const void*  coord = d_in[1];
    const void*  valid = d_in[2];
    const float* W     = (const float*)d_in[3];
    const float* pos   = (const float*)d_in[4];
    float* out = (float*)d_out;

    cudaFuncSetAttribute(gemm_kernel,
                         cudaFuncAttributeMaxDynamicSharedMemorySize, SMEM_BYTES);

    int do_aux = ((size_t)out_size >= OUT_TOTAL) ? 1 : 0;
    prologue_kernel<<<PRO_BLOCKS, 256>>>(
        x, W, coord, valid,
        out + OUT_Y, out + OUT_Y + OUT_PID, do_aux);

    dim3 grid(DIM / BN, MROWS / BM);   // (6, 256)
    gemm_kernel<<<grid, 256, SMEM_BYTES>>>(pos, out);
}

// round 16
// speedup vs baseline: 1.3612x; 1.3612x over previous
#include <cuda_runtime.h>
#include <cuda_fp16.h>
#include <cstdint>

// Problem constants
#define MROWS   32768
#define DIM     768
#define VPOS    10240
#define POS_OFF ((size_t)VPOS * DIM)

// GEMM tiling: CTA 128x128, 8 warps (2m x 4n), warp tile 64x32
// fp16 operands, fp32 accumulate. BK=64, 3-stage cp.async pipeline, 1 sync/tile.
// Operands live in gmem in TILE-MAJOR layout: tile (128 rows x 64 k) = 16KB
// contiguous, k-permute (k=16g+8h+2c+e -> 8c+4g+2h+e per 32-chunk) and
// row-parity 64B-chunk swizzle pre-baked -> smem is a verbatim copy and every
// cp.async uses a purely linear offset (no per-chunk address ALU).
#define BM 128
#define BN 128
#define BK 64
#define NKT (DIM / BK)              // 12
#define TB 16384                    // bytes per operand tile
#define STAGE_B (2 * TB)            // A + B = 32768
#define NSTAGE 3
#define SMEM_BYTES (NSTAGE * STAGE_B)  // 98304

// Fused prologue block ranges
#define XPREP_BLOCKS ((MROWS * 96) / 256)   // 12288
#define PREP_BLOCKS  DIM                    // 768
#define NORM_BLOCKS  (MROWS / 256)          // 128
#define PRO_BLOCKS   (XPREP_BLOCKS + PREP_BLOCKS + NORM_BLOCKS)

// Output layout (flattened concat of the reference tuple, as float32)
#define OUT_Y     ((size_t)MROWS * DIM)
#define OUT_PID   ((size_t)MROWS * 2)
#define OUT_TOTAL (OUT_Y + OUT_PID + (size_t)MROWS)

// Device scratch (tile-major operand buffers)
__device__ __align__(128) unsigned char g_Xb[(size_t)(MROWS / 128) * NKT * TB]; // 48MB
__device__ __align__(128) unsigned char g_Wb[(size_t)(DIM / 128) * NKT * TB];   // 1.125MB
__device__ float g_bias[DIM];       // -sum_k W[d,k]
__device__ int g_pid0[MROWS];
__device__ int g_pid1[MROWS];
__device__ unsigned char g_ok[MROWS];

__device__ __forceinline__ void cp_async16(uint32_t s, const void* g) {
    asm volatile("cp.async.cg.shared.global [%0], [%1], 16;\n" :: "r"(s), "l"(g));
}

__device__ __forceinline__ void mma_fp16(float* c,
                                         uint32_t a0, uint32_t a1, uint32_t a2, uint32_t a3,
                                         uint32_t b0, uint32_t b1) {
    asm volatile(
        "mma.sync.aligned.m16n8k16.row.col.f32.f16.f16.f32 "
        "{%0,%1,%2,%3}, {%4,%5,%6,%7}, {%8,%9}, {%0,%1,%2,%3};\n"
        : "+f"(c[0]), "+f"(c[1]), "+f"(c[2]), "+f"(c[3])
        : "r"(a0), "r"(a1), "r"(a2), "r"(a3), "r"(b0), "r"(b1));
}

// ---------------------------------------------------------------------------
// Fused prologue: one launch, three independent block ranges.
//   [0, XPREP_BLOCKS)            : fp16-convert + permute + TILE x into g_Xb
//   [XPREP_BLOCKS, +PREP_BLOCKS) : weight permute/scale/round + TILE + bias
//   [rest, +NORM_BLOCKS)         : self-detecting coord/valid normalize + aux
// ---------------------------------------------------------------------------
__global__ void __launch_bounds__(256) prologue_kernel(
    const float* __restrict__ x,
    const float* __restrict__ W,
    const void*  coordp,
    const void*  validp,
    float* __restrict__ out_pid,
    float* __restrict__ out_pad,
    int do_aux)
{
    const int bid = blockIdx.x;
    const int tid = threadIdx.x;

    if (bid < XPREP_BLOCKS) {
        // ---- xprep: k=16g+8h+2c+e -> phys=8c+4g+2h+e, tiled destination ----
        unsigned int idx = bid * 256 + tid;              // < MROWS*96
        unsigned int row = idx / 96;
        unsigned int u = idx - row * 96;
        unsigned int ci = u >> 2, c = u & 3;
        const float* src = x + (size_t)row * DIM + ci * 32 + 2 * c;
        float2 p00 = *reinterpret_cast<const float2*>(src);
        float2 p01 = *reinterpret_cast<const float2*>(src + 8);
        float2 p10 = *reinterpret_cast<const float2*>(src + 16);
        float2 p11 = *reinterpret_cast<const float2*>(src + 24);
        __half2 h00 = __floats2half2_rn(p00.x, p00.y);
        __half2 h01 = __floats2half2_rn(p01.x, p01.y);
        __half2 h10 = __floats2half2_rn(p10.x, p10.y);
        __half2 h11 = __floats2half2_rn(p11.x, p11.y);
        uint4 o;
        o.x = *reinterpret_cast<uint32_t*>(&h00);
        o.y = *reinterpret_cast<uint32_t*>(&h01);
        o.z = *reinterpret_cast<uint32_t*>(&h10);
        o.w = *reinterpret_cast<uint32_t*>(&h11);
        unsigned int rb = row >> 7, r = row & 127;
        unsigned int kt = ci >> 1, ch = ci & 1;
        size_t off = ((size_t)(rb * NKT + kt) << 14) + r * 128 + ((ch ^ (r & 1)) << 6) + c * 16;
        *reinterpret_cast<uint4*>(g_Xb + off) = o;
        return;
    }

    if (bid < XPREP_BLOCKS + PREP_BLOCKS) {
        // ---- prep: weights (tiled destination) ----
        int d = bid - XPREP_BLOCKS;
        const float* wrow = W + (size_t)d * DIM;
        int nb = d >> 7, r = d & 127;
        __shared__ float red[256];
        float s = 0.f;
        for (int jp = tid; jp < DIM; jp += 256) {
            int ci = jp >> 5, p = jp & 31;
            int c = p >> 3, g = (p >> 2) & 1, h = (p >> 1) & 1, e = p & 1;
            int j = ci * 32 + 16 * g + 8 * h + 2 * c + e;  // logical column
            int c3 = j % 3;
            int tt = j / 3;
            int pw = tt & 15;
            int ph = tt >> 4;
            int k = c3 * 256 + ph * 16 + pw;
            float w = wrow[k];
            s += w;
            int kt = ci >> 1, ch = ci & 1;
            size_t off = ((size_t)(nb * NKT + kt) << 14) + r * 128 + ((ch ^ (r & 1)) << 6) + p * 2;
            *reinterpret_cast<__half*>(g_Wb + off) = __float2half_rn(2.0f * w);
        }
        red[tid] = s;
        __syncthreads();
        for (int off = 128; off > 0; off >>= 1) {
            if (tid < off) red[tid] += red[tid + off];
            __syncthreads();
        }
        if (tid == 0) g_bias[d] = -red[0];
        return;
    }

    // ---- norm (+self-detect) + aux ----
    {
        __shared__ unsigned int s_or_all, s_or_odd, s_vb_or, s_vb_gt1;
        __shared__ int sh_cf, sh_vf;
        if (tid == 0) { s_or_all = 0; s_or_odd = 0; s_vb_or = 0; s_vb_gt1 = 0; }
        __syncthreads();

        const unsigned int* cw = (const unsigned int*)coordp;
        unsigned int oa = 0, oo = 0;
        for (int i = tid; i < 2048; i += 256) {
            unsigned int w = cw[i];
            oa |= w;
            if (i & 1) oo |= w;
        }
        atomicOr(&s_or_all, oa);
        atomicOr(&s_or_odd, oo);

        const unsigned char* vb = (const unsigned char*)validp;
        unsigned int vo = 0, vg = 0;
        for (int i = tid; i < 4096; i += 256) {
            unsigned char b = vb[i];
            if (i & 3) vo |= b;
            if (b > 1) vg = 1;
        }
        atomicOr(&s_vb_or, vo);
        atomicOr(&s_vb_gt1, vg);
        __syncthreads();

        if (tid == 0) {
            sh_cf = (s_or_all >= 0x10000u) ? 2 : (s_or_odd == 0 ? 1 : 0);
            sh_vf = s_vb_gt1 ? 2 : (s_vb_or == 0 ? 0 : 1);
        }
        __syncthreads();
        int cf = sh_cf, vf = sh_vf;

        int i = (bid - XPREP_BLOCKS - PREP_BLOCKS) * 256 + tid;   // < MROWS
        int c0, c1;
        if (cf == 1) {
            const long long* c = (const long long*)coordp;
            c0 = (int)c[2LL * i]; c1 = (int)c[2LL * i + 1];
        } else if (cf == 2) {
            const float* c = (const float*)coordp;
            c0 = (int)c[2LL * i]; c1 = (int)c[2LL * i + 1];
        } else {
            const int* c = (const int*)coordp;
            c0 = c[2 * i]; c1 = c[2 * i + 1];
        }
        g_pid0[i] = c1 > 0 ? c1 : 0;
        g_pid1[i] = c0 > 0 ? c0 : 0;

        bool v;
        if (vf == 0)      v = ((const int*)validp)[i] != 0;
        else if (vf == 2) v = ((const float*)validp)[i] != 0.0f;
        else              v = ((const unsigned char*)validp)[i] != 0;
        g_ok[i] = v ? 1 : 0;

        if (do_aux) {
            out_pid[2LL * i]     = (float)c1;
            out_pid[2LL * i + 1] = (float)c0;
            out_pad[i] = v ? 0.0f : 1.0f;
        }
    }
}

// ---------------------------------------------------------------------------
// Main fused GEMM: y = Xh @ Wh^T + bias + pos(gather), fp16 m16n8k16 warp MMA
// grid (6, 256), 256 threads, 3-stage distributed cp.async pipeline (linear
// addressing from tile-major gmem), 1 sync per k-tile.
// ---------------------------------------------------------------------------
__global__ void __launch_bounds__(256, 2)
gemm_kernel(const float* __restrict__ pos_table,
            float* __restrict__ out) {
    extern __shared__ char smem[];
    const int tid = threadIdx.x;

    const int lane = tid & 31;
    const int warp = tid >> 5;
    const int wm = warp & 1;   // 0..1  (m, 64 rows each)
    const int wn = warp >> 1;  // 0..3  (n, 32 cols each)
    const int q = lane >> 2;   // 0..7
    const int c = lane & 3;    // 0..3
    const int parq = q & 1;

    const unsigned char* Asrc = g_Xb + (size_t)blockIdx.y * NKT * TB + tid * 16;
    const unsigned char* Bsrc = g_Wb + (size_t)blockIdx.x * NKT * TB + tid * 16;

    // async load of tile kt into stage slot: verbatim copy, linear offsets
    auto issue = [&](int kt, int slot) {
        char* Ss = smem + slot * STAGE_B + tid * 16;
        const unsigned char* Ag = Asrc + (size_t)kt * TB;
        const unsigned char* Bg = Bsrc + (size_t)kt * TB;
        #pragma unroll
        for (int i = 0; i < 4; i++) {
            cp_async16((uint32_t)__cvta_generic_to_shared(Ss + i * 4096), Ag + i * 4096);
            cp_async16((uint32_t)__cvta_generic_to_shared(Ss + TB + i * 4096), Bg + i * 4096);
        }
        asm volatile("cp.async.commit_group;\n");
    };

    issue(0, 0);
    issue(1, 1);

    float acc[4][4][4];
    #pragma unroll
    for (int a = 0; a < 4; a++)
        #pragma unroll
        for (int b = 0; b < 4; b++)
            #pragma unroll
            for (int k = 0; k < 4; k++) acc[a][b][k] = 0.f;

    // Prefetch epilogue row metadata
    int ep_p0[8], ep_p1[8];
    unsigned char ep_ok[8];
    {
        const int gm0 = blockIdx.y * BM + wm * 64;
        #pragma unroll
        for (int im = 0; im < 4; im++) {
            #pragma unroll
            for (int half = 0; half < 2; half++) {
                int r = gm0 + im * 16 + q + half * 8;
                ep_p0[im * 2 + half] = g_pid0[r];
                ep_p1[im * 2 + half] = g_pid1[r];
                ep_ok[im * 2 + half] = g_ok[r];
            }
        }
    }

    for (int kt = 0; kt < NKT; kt++) {
        const int slot = kt % NSTAGE;
        if (kt + 1 < NKT) {
            asm volatile("cp.async.wait_group 1;\n");
        } else {
            asm volatile("cp.async.wait_group 0;\n");
        }
        __syncthreads();           // kt data visible AND kt-1 readers done
        if (kt + 2 < NKT) issue(kt + 2, (kt + 2) % NSTAGE);

        const char* Ss = smem + slot * STAGE_B;
        const char* Als = Ss + (wm * 64 + q) * 128 + c * 16;
        const char* Bls = Ss + TB + (wn * 32 + q) * 128 + c * 16;

        #pragma unroll
        for (int ci = 0; ci < 2; ci++) {
            const int g = ((ci ^ parq) << 6);   // swizzled 32-chunk offset (bytes)
            uint4 Aq[4][2];
            uint4 Bq[4];
            #pragma unroll
            for (int im = 0; im < 4; im++) {
                Aq[im][0] = *reinterpret_cast<const uint4*>(Als + im * 2048 + g);
                Aq[im][1] = *reinterpret_cast<const uint4*>(Als + im * 2048 + 1024 + g);
            }
            #pragma unroll
            for (int in = 0; in < 4; in++)
                Bq[in] = *reinterpret_cast<const uint4*>(Bls + in * 1024 + g);

            #pragma unroll
            for (int im = 0; im < 4; im++)
                #pragma unroll
                for (int in = 0; in < 4; in++)
                    mma_fp16(acc[im][in],
                             Aq[im][0].x, Aq[im][1].x, Aq[im][0].y, Aq[im][1].y,
                             Bq[in].x, Bq[in].y);
            #pragma unroll
            for (int im = 0; im < 4; im++)
                #pragma unroll
                for (int in = 0; in < 4; in++)
                    mma_fp16(acc[im][in],
                             Aq[im][0].z, Aq[im][1].z, Aq[im][0].w, Aq[im][1].w,
                             Bq[in].z, Bq[in].w);
        }
    }

    // Epilogue: + bias + pos gather, write float2
    const int gm0 = blockIdx.y * BM + wm * 64;
    const int gn0 = blockIdx.x * BN + wn * 32;

    #pragma unroll
    for (int im = 0; im < 4; im++) {
        int rbase = gm0 + im * 16 + q;
        #pragma unroll
        for (int half = 0; half < 2; half++) {
            int r = rbase + half * 8;
            int p0 = ep_p0[im * 2 + half];
            int p1 = ep_p1[im * 2 + half];
            bool v = (ep_ok[im * 2 + half] != 0);
            const float* t0 = pos_table + (size_t)p0 * DIM;
            const float* t1 = pos_table + POS_OFF + (size_t)p1 * DIM;
            float* orow = out + (size_t)r * DIM;
            #pragma unroll
            for (int in = 0; in < 4; in++) {
                int d = gn0 + in * 8 + c * 2;
                float v0 = acc[im][in][half * 2 + 0] + g_bias[d];
                float v1 = acc[im][in][half * 2 + 1] + g_bias[d + 1];
                if (v) {
                    v0 += t0[d] + t1[d];
                    v1 += t0[d + 1] + t1[d + 1];
                }
                float2 o; o.x = v0; o.y = v1;
                *reinterpret_cast<float2*>(&orow[d]) = o;
            }
        }
    }
}

extern "C" void kernel_launch(void* const* d_in, const int* in_sizes, int n_in,
                              void* d_out, int out_size) {
    const float* x     = (const float*)d_in[0];
    const void*  coord = d_in[1];
    const void*  valid = d_in[2];
    const float* W     = (const float*)d_in[3];
    const float* pos   = (const float*)d_in[4];
    float* out = (float*)d_out;

    cudaFuncSetAttribute(gemm_kernel,
                         cudaFuncAttributeMaxDynamicSharedMemorySize, SMEM_BYTES);

    int do_aux = ((size_t)out_size >= OUT_TOTAL) ? 1 : 0;
    prologue_kernel<<<PRO_BLOCKS, 256>>>(
        x, W, coord, valid,
        out + OUT_Y, out + OUT_Y + OUT_PID, do_aux);

    dim3 grid(DIM / BN, MROWS / BM);   // (6, 256)
    gemm_kernel<<<grid, 256, SMEM_BYTES>>>(pos, out);
}